// round 11
// baseline (speedup 1.0000x reference)
#include <cuda_runtime.h>

// EnergyGatedDeltaModel — GB300 sm_103a
// R10: always-exact paired gate (no butterflies, no THRESH, no rebuild path).
// Every step computes the reference's NEON-ordered ||Mn||^2 chain (lanes 0-15
// batch A, 16-31 batch B) and compares against the cached scalar eo (= en at
// last accept; bit-identical to recomputing ||M||^2 since M is unchanged).
// All fp expressions/orderings identical to R6/R8 => identical outputs.

#define B_ 512
#define L_ 2048
#define H_ 32
#define V_ 64
#define STEPS (L_ - 1)
#define ROWP 36
#define BUFB (H_ * ROWP + 16)   // B buffer offset: shifts banks by 16 -> conflict-free split LDS

__device__ float g_table[V_ * H_];
__device__ float g_denom[V_];
__device__ int   g_writes;

// NEON VF4xIC4 reduction of 32 products (R6-identical values).
__device__ __forceinline__ float neon_dot32(const float* x, const float* y) {
    float A[16];
#pragma unroll
    for (int c = 0; c < 16; c++) A[c] = __fmul_rn(x[c], y[c]);
#pragma unroll
    for (int c = 0; c < 16; c++) A[c] = fmaf(x[16 + c], y[16 + c], A[c]);
    float V[4];
#pragma unroll
    for (int l = 0; l < 4; l++)
        V[l] = __fadd_rn(__fadd_rn(__fadd_rn(A[l], A[4 + l]), A[8 + l]), A[12 + l]);
    return __fadd_rn(__fadd_rn(V[0], V[2]), __fadd_rn(V[1], V[3]));
}

__device__ __forceinline__ float neon_sum32(const float* t) {
    float A[16];
#pragma unroll
    for (int c = 0; c < 16; c++) A[c] = __fadd_rn(t[c], t[16 + c]);
    float V[4];
#pragma unroll
    for (int l = 0; l < 4; l++)
        V[l] = __fadd_rn(__fadd_rn(__fadd_rn(A[l], A[4 + l]), A[8 + l]), A[12 + l]);
    return __fadd_rn(__fadd_rn(V[0], V[2]), __fadd_rn(V[1], V[3]));
}

// ---------------------------------------------------------------------------
__global__ void precompute_kernel(const float* __restrict__ embed,
                                  const float* __restrict__ w1,
                                  const float* __restrict__ b1,
                                  const float* __restrict__ w2,
                                  const float* __restrict__ b2,
                                  const float* __restrict__ ln_g,
                                  const float* __restrict__ ln_b)
{
    __shared__ float h_sh[H_];
    __shared__ float s_sh[2 * H_];
    __shared__ float x_sh[H_];

    const int v = blockIdx.x;
    const int t = threadIdx.x;
    if (v == 0 && t == 0) g_writes = 0;

    if (t < H_) h_sh[t] = embed[v * H_ + t];
    __syncthreads();

    {
        const int j = t;
        float s = 0.0f;
#pragma unroll
        for (int i = 0; i < H_; i++) s = fmaf(h_sh[i], w1[i * 2 * H_ + j], s);
        s = __fadd_rn(s, b1[j]);
        s_sh[j] = fmaxf(s, 0.0f);
    }
    __syncthreads();

    if (t < H_) {
        const int i = t;
        float acc = 0.0f;
#pragma unroll
        for (int j = 0; j < 2 * H_; j++) acc = fmaf(s_sh[j], w2[j * H_ + i], acc);
        float ff = __fadd_rn(acc, b2[i]);
        x_sh[i] = __fadd_rn(h_sh[i], ff);
    }
    __syncthreads();

    if (t == 0) {
        float x[H_], d[H_], sq[H_];
#pragma unroll
        for (int i = 0; i < H_; i++) x[i] = x_sh[i];
        float mu = __fmul_rn(neon_sum32(x), 1.0f / H_);
#pragma unroll
        for (int i = 0; i < H_; i++) {
            d[i] = __fsub_rn(x[i], mu);
            sq[i] = __fmul_rn(d[i], d[i]);
        }
        float var = __fmul_rn(neon_sum32(sq), 1.0f / H_);
        float rs = __fdiv_rn(1.0f, __fsqrt_rn(__fadd_rn(var, 1e-5f)));
        float y[H_];
#pragma unroll
        for (int i = 0; i < H_; i++) {
            y[i] = __fadd_rn(__fmul_rn(__fmul_rn(d[i], rs), ln_g[i]), ln_b[i]);
            g_table[v * H_ + i] = y[i];
            sq[i] = __fmul_rn(y[i], y[i]);
        }
        float ksq = neon_sum32(sq);
        g_denom[v] = __fadd_rn(ksq, 1e-6f);
    }
}

// ---------------------------------------------------------------------------
// 64-step fma chain for accumulator c (NEON-ordered 1024-sum; R6-identical).
__device__ __forceinline__ float chain64(const float* P, int c) {
    float a = 0.0f;
#pragma unroll
    for (int m = 0; m < 64; m++) {
        float s = P[(m >> 1) * ROWP + (m & 1) * 16 + c];
        a = fmaf(s, s, a);
    }
    return a;
}

// NEON fold of 16 chain accumulators living in lanes base..base+15.
__device__ __forceinline__ float fold16(float val, int base, unsigned FULL) {
    float V[4];
#pragma unroll
    for (int l = 0; l < 4; l++) {
        float a0 = __shfl_sync(FULL, val, base + l);
        float a1 = __shfl_sync(FULL, val, base + l + 4);
        float a2 = __shfl_sync(FULL, val, base + l + 8);
        float a3 = __shfl_sync(FULL, val, base + l + 12);
        V[l] = __fadd_rn(__fadd_rn(__fadd_rn(a0, a1), a2), a3);
    }
    return __fadd_rn(__fadd_rn(V[0], V[2]), __fadd_rn(V[1], V[3]));
}

// Store candidate row Mn = fma(u,k,M) straight to smem (no register copy).
__device__ __forceinline__ void store_row_mn(float* buf, int lane, const float* Mrow,
                                             float u, const float* k) {
    float4* p = (float4*)(buf + lane * ROWP);
#pragma unroll
    for (int q = 0; q < 8; q++)
        p[q] = make_float4(fmaf(u, k[4*q],   Mrow[4*q]),
                           fmaf(u, k[4*q+1], Mrow[4*q+1]),
                           fmaf(u, k[4*q+2], Mrow[4*q+2]),
                           fmaf(u, k[4*q+3], Mrow[4*q+3]));
}

// ---------------------------------------------------------------------------
__global__ void __launch_bounds__(32) scan_kernel(const int* __restrict__ seq,
                                                  const float* __restrict__ w_read,
                                                  const float* __restrict__ b_read,
                                                  const float* __restrict__ w_out,
                                                  const float* __restrict__ b_out,
                                                  float* __restrict__ out)
{
    __shared__ __align__(16) float tsh[V_ * H_];
    __shared__ __align__(16) float slowbuf[BUFB + H_ * ROWP];
    __shared__ float dnsh[V_];
    __shared__ int   toksA[32];
    __shared__ int   toksB[32];
    __shared__ float scratch[H_];

    const int lane = threadIdx.x;
    const int bA   = blockIdx.x;
    const int bB   = blockIdx.x + 256;
    const unsigned FULL = 0xffffffffu;
    float* bufA = slowbuf;
    float* bufB = slowbuf + BUFB;

    for (int i = lane; i < V_ * H_; i += 32) tsh[i] = g_table[i];
    dnsh[lane]      = g_denom[lane];
    dnsh[lane + 32] = g_denom[lane + 32];
    __syncwarp();

    float MA[H_], MB[H_];
#pragma unroll
    for (int j = 0; j < H_; j++) { MA[j] = 0.0f; MB[j] = 0.0f; }

    float eoA = 0.0f, eoB = 0.0f;   // cached ||M||^2 (exact: en at last accept; 0 for M=0)
    float vA = 0.0f, vB = 0.0f;     // pipelined dot(M, k_cur)
    int writes = 0;
    const int* sA = seq + bA * L_;
    const int* sB = seq + bB * L_;

    for (int t0 = 0; t0 < STEPS; t0 += 32) {
        toksA[lane] = sA[t0 + lane];
        toksB[lane] = sB[t0 + lane];
        __syncwarp();
        const int nfA = (t0 + 32 < L_) ? sA[t0 + 32] : 0;
        const int nfB = (t0 + 32 < L_) ? sB[t0 + 32] : 0;
        const int tend = (STEPS - t0) < 32 ? (STEPS - t0) : 32;

        if (t0 == 0) {   // prologue dots (M=0 -> exactly 0, same expression)
            vA = neon_dot32(MA, tsh + toksA[0] * H_);
            vB = neon_dot32(MB, tsh + toksB[0] * H_);
        }

        for (int tt = 0; tt < tend; tt++) {
            const int tokA = toksA[tt];
            const int tokB = toksB[tt];
            const int tokAn = (tt + 1 < 32) ? toksA[tt + 1] : nfA;
            const int tokBn = (tt + 1 < 32) ? toksB[tt + 1] : nfB;
            const float* kA  = tsh + tokA * H_;
            const float* kB  = tsh + tokB * H_;

            // u = k - v/denom (IEEE div + sub, unfused)
            const float uA = __fsub_rn(kA[lane], __fdiv_rn(vA, dnsh[tokA]));
            const float uB = __fsub_rn(kB[lane], __fdiv_rn(vB, dnsh[tokB]));

            // candidate rows straight to smem
            store_row_mn(bufA, lane, MA, uA, kA);
            store_row_mn(bufB, lane, MB, uB, kB);
            __syncwarp();

            // paired exact chains: lanes 0-15 -> A, 16-31 -> B
            float a = chain64((lane < 16) ? bufA : bufB, lane & 15);

            const float enA = fold16(a, 0, FULL);
            const float enB = fold16(a, 16, FULL);
            const int gateA = enA > eoA;
            const int gateB = enB > eoB;

            if (gateA) {
                writes++;
                eoA = enA;
#pragma unroll
                for (int j = 0; j < H_; j++) MA[j] = fmaf(uA, kA[j], MA[j]);
            }
            if (gateB) {
                writes++;
                eoB = enB;
#pragma unroll
                for (int j = 0; j < H_; j++) MB[j] = fmaf(uB, kB[j], MB[j]);
            }

            // next-step dots on the selected state
            vA = neon_dot32(MA, tsh + tokAn * H_);
            vB = neon_dot32(MB, tsh + tokBn * H_);
            __syncwarp();   // WAR: chain reads done before next store
        }
    }

    // -------- readout (both batches), identical arithmetic --------
#pragma unroll
    for (int pass = 0; pass < 2; pass++) {
        const int b = pass ? bB : bA;
        const float* M = pass ? MB : MA;
        const int qtok = (pass ? sB : sA)[L_ - 1];
        const float* qv = tsh + qtok * H_;
        float ctx = neon_dot32(M, qv);

        scratch[lane] = ctx;
        __syncwarp();
        float r = 0.0f;
#pragma unroll
        for (int j = 0; j < H_; j++) r = fmaf(scratch[j], w_read[j * H_ + lane], r);
        r = __fadd_rn(r, b_read[lane]);
        __syncwarp();
        scratch[lane] = r;
        __syncwarp();

        float o0 = 0.0f, o1 = 0.0f;
#pragma unroll
        for (int j = 0; j < H_; j++) {
            const float rj = scratch[j];
            o0 = fmaf(rj, w_out[j * V_ + lane], o0);
            o1 = fmaf(rj, w_out[j * V_ + lane + H_], o1);
        }
        out[b * V_ + lane]      = __fadd_rn(o0, b_out[lane]);
        out[b * V_ + lane + H_] = __fadd_rn(o1, b_out[lane + H_]);
        __syncwarp();
    }

    if (lane == 0) atomicAdd(&g_writes, writes);
}

// ---------------------------------------------------------------------------
__global__ void finalize_kernel(float* __restrict__ out, int out_size)
{
    if (out_size > B_ * V_)
        out[B_ * V_] = __fdiv_rn((float)g_writes, (float)(STEPS * B_));
}

extern "C" void kernel_launch(void* const* d_in, const int* in_sizes, int n_in,
                              void* d_out, int out_size)
{
    const int*   seq    = (const int*)d_in[0];
    const float* embed  = (const float*)d_in[1];
    const float* w1     = (const float*)d_in[2];
    const float* b1     = (const float*)d_in[3];
    const float* w2     = (const float*)d_in[4];
    const float* b2     = (const float*)d_in[5];
    const float* ln_g   = (const float*)d_in[6];
    const float* ln_b   = (const float*)d_in[7];
    const float* w_read = (const float*)d_in[8];
    const float* b_read = (const float*)d_in[9];
    const float* w_out  = (const float*)d_in[10];
    const float* b_out  = (const float*)d_in[11];
    float* out = (float*)d_out;

    precompute_kernel<<<V_, 64>>>(embed, w1, b1, w2, b2, ln_g, ln_b);
    scan_kernel<<<B_ / 2, 32>>>(seq, w_read, b_read, w_out, b_out, out);
    finalize_kernel<<<1, 1>>>(out, out_size);
}

// round 12
// speedup vs baseline: 2.0596x; 2.0596x over previous
#include <cuda_runtime.h>

// EnergyGatedDeltaModel — GB300 sm_103a
// R11 = R8 structure (butterfly fast gate + paired exact slow path, bit-identical
// decisions) with three scheduling/layout fixes:
//  1. chain64: explicit 16-wide load prefetch (same fma order) — kills the
//     per-link 29-cyc LDS dependent latency seen in R10.
//  2. slow-path buffers staggered +16 banks pairwise -> conflict-free chains.
//  3. aold[16] replaced by cached scalar eo (== fold16(aold), deterministic).

#define B_ 512
#define L_ 2048
#define H_ 32
#define V_ 64
#define STEPS (L_ - 1)
#define THRESH 1.0f
#define ROWP 36
// word offsets inside slowbuf; pairwise deltas ≡ 16 (mod 32 banks), 16B-aligned
#define OFF_MNA 0
#define OFF_MNB 1168
#define OFF_MOA 2352
#define OFF_MOB 3520
#define SLOWBUF_WORDS (OFF_MOB + H_ * ROWP)

__device__ float g_table[V_ * H_];
__device__ float g_ksq[V_];
__device__ float g_denom[V_];
__device__ int   g_writes;

// NEON VF4xIC4 reduction of 32 products (R6-identical values).
__device__ __forceinline__ float neon_dot32(const float* x, const float* y) {
    float A[16];
#pragma unroll
    for (int c = 0; c < 16; c++) A[c] = __fmul_rn(x[c], y[c]);
#pragma unroll
    for (int c = 0; c < 16; c++) A[c] = fmaf(x[16 + c], y[16 + c], A[c]);
    float V[4];
#pragma unroll
    for (int l = 0; l < 4; l++)
        V[l] = __fadd_rn(__fadd_rn(__fadd_rn(A[l], A[4 + l]), A[8 + l]), A[12 + l]);
    return __fadd_rn(__fadd_rn(V[0], V[2]), __fadd_rn(V[1], V[3]));
}

__device__ __forceinline__ float neon_sum32(const float* t) {
    float A[16];
#pragma unroll
    for (int c = 0; c < 16; c++) A[c] = __fadd_rn(t[c], t[16 + c]);
    float V[4];
#pragma unroll
    for (int l = 0; l < 4; l++)
        V[l] = __fadd_rn(__fadd_rn(__fadd_rn(A[l], A[4 + l]), A[8 + l]), A[12 + l]);
    return __fadd_rn(__fadd_rn(V[0], V[2]), __fadd_rn(V[1], V[3]));
}

// ---------------------------------------------------------------------------
__global__ void precompute_kernel(const float* __restrict__ embed,
                                  const float* __restrict__ w1,
                                  const float* __restrict__ b1,
                                  const float* __restrict__ w2,
                                  const float* __restrict__ b2,
                                  const float* __restrict__ ln_g,
                                  const float* __restrict__ ln_b)
{
    __shared__ float h_sh[H_];
    __shared__ float s_sh[2 * H_];
    __shared__ float x_sh[H_];

    const int v = blockIdx.x;
    const int t = threadIdx.x;
    if (v == 0 && t == 0) g_writes = 0;

    if (t < H_) h_sh[t] = embed[v * H_ + t];
    __syncthreads();

    {
        const int j = t;
        float s = 0.0f;
#pragma unroll
        for (int i = 0; i < H_; i++) s = fmaf(h_sh[i], w1[i * 2 * H_ + j], s);
        s = __fadd_rn(s, b1[j]);
        s_sh[j] = fmaxf(s, 0.0f);
    }
    __syncthreads();

    if (t < H_) {
        const int i = t;
        float acc = 0.0f;
#pragma unroll
        for (int j = 0; j < 2 * H_; j++) acc = fmaf(s_sh[j], w2[j * H_ + i], acc);
        float ff = __fadd_rn(acc, b2[i]);
        x_sh[i] = __fadd_rn(h_sh[i], ff);
    }
    __syncthreads();

    if (t == 0) {
        float x[H_], d[H_], sq[H_];
#pragma unroll
        for (int i = 0; i < H_; i++) x[i] = x_sh[i];
        float mu = __fmul_rn(neon_sum32(x), 1.0f / H_);
#pragma unroll
        for (int i = 0; i < H_; i++) {
            d[i] = __fsub_rn(x[i], mu);
            sq[i] = __fmul_rn(d[i], d[i]);
        }
        float var = __fmul_rn(neon_sum32(sq), 1.0f / H_);
        float rs = __fdiv_rn(1.0f, __fsqrt_rn(__fadd_rn(var, 1e-5f)));
        float y[H_];
#pragma unroll
        for (int i = 0; i < H_; i++) {
            y[i] = __fadd_rn(__fmul_rn(__fmul_rn(d[i], rs), ln_g[i]), ln_b[i]);
            g_table[v * H_ + i] = y[i];
            sq[i] = __fmul_rn(y[i], y[i]);
        }
        float ksq = neon_sum32(sq);
        g_ksq[v]   = ksq;
        g_denom[v] = __fadd_rn(ksq, 1e-6f);
    }
}

// ---------------------------------------------------------------------------
// Slow-path primitives (values identical to R8).
// ---------------------------------------------------------------------------

// NEON-ordered 1024-chain accumulator c, with explicit 16-wide load prefetch.
__device__ __forceinline__ float chain64p(const float* P, int c) {
    float a = 0.0f;
#pragma unroll
    for (int g = 0; g < 4; g++) {
        float s[16];
#pragma unroll
        for (int i = 0; i < 16; i++) {
            const int m = g * 16 + i;
            s[i] = P[(m >> 1) * ROWP + (m & 1) * 16 + c];
        }
#pragma unroll
        for (int i = 0; i < 16; i++)
            a = fmaf(s[i], s[i], a);
    }
    return a;
}

__device__ __forceinline__ float fold16(float val, int base, unsigned FULL) {
    float V[4];
#pragma unroll
    for (int l = 0; l < 4; l++) {
        float a0 = __shfl_sync(FULL, val, base + l);
        float a1 = __shfl_sync(FULL, val, base + l + 4);
        float a2 = __shfl_sync(FULL, val, base + l + 8);
        float a3 = __shfl_sync(FULL, val, base + l + 12);
        V[l] = __fadd_rn(__fadd_rn(__fadd_rn(a0, a1), a2), a3);
    }
    return __fadd_rn(__fadd_rn(V[0], V[2]), __fadd_rn(V[1], V[3]));
}

__device__ __forceinline__ void store_row(float* buf, int lane, const float* Mrow) {
    float4* p = (float4*)(buf + lane * ROWP);
#pragma unroll
    for (int q = 0; q < 8; q++)
        p[q] = make_float4(Mrow[4*q], Mrow[4*q+1], Mrow[4*q+2], Mrow[4*q+3]);
}

__device__ __forceinline__ void store_row_mn(float* buf, int lane, const float* Mrow,
                                             float u, const float* k) {
    float4* p = (float4*)(buf + lane * ROWP);
#pragma unroll
    for (int q = 0; q < 8; q++)
        p[q] = make_float4(fmaf(u, k[4*q],   Mrow[4*q]),
                           fmaf(u, k[4*q+1], Mrow[4*q+1]),
                           fmaf(u, k[4*q+2], Mrow[4*q+2]),
                           fmaf(u, k[4*q+3], Mrow[4*q+3]));
}

// Single-batch exact gate with cached eo scalar (== fold16 of M's chain).
__device__ __forceinline__ int resolve_single(const float* M, float u, const float* k,
                                              float& eo, bool& valid,
                                              float* mnbuf, float* mobuf,
                                              int lane, unsigned FULL)
{
    int g;
    if (valid) {
        store_row_mn(mnbuf, lane, M, u, k);
        __syncwarp();
        float a = 0.0f;
        if (lane < 16) a = chain64p(mnbuf, lane);
        __syncwarp();
        float en = fold16(a, 0, FULL);
        g = en > eo;
        if (g) eo = en;
    } else {
        store_row(mobuf, lane, M);
        store_row_mn(mnbuf, lane, M, u, k);
        __syncwarp();
        float a = chain64p((lane < 16) ? mobuf : mnbuf, lane & 15);
        __syncwarp();
        float eoc = fold16(a, 0, FULL);
        float en  = fold16(a, 16, FULL);
        g = en > eoc;
        eo = g ? en : eoc;
        valid = true;
    }
    return g;
}

// ---------------------------------------------------------------------------
__global__ void __launch_bounds__(32) scan_kernel(const int* __restrict__ seq,
                                                  const float* __restrict__ w_read,
                                                  const float* __restrict__ b_read,
                                                  const float* __restrict__ w_out,
                                                  const float* __restrict__ b_out,
                                                  float* __restrict__ out)
{
    __shared__ __align__(16) float tsh[V_ * H_];
    __shared__ __align__(16) float slowbuf[SLOWBUF_WORDS];
    __shared__ float dnsh[V_];
    __shared__ float kssh[V_];
    __shared__ int   toksA[32];
    __shared__ int   toksB[32];
    __shared__ float scratch[H_];

    const int lane = threadIdx.x;
    const int bA   = blockIdx.x;
    const int bB   = blockIdx.x + 256;
    const unsigned FULL = 0xffffffffu;
    float* mnA = slowbuf + OFF_MNA;
    float* mnB = slowbuf + OFF_MNB;
    float* moA = slowbuf + OFF_MOA;
    float* moB = slowbuf + OFF_MOB;

    for (int i = lane; i < V_ * H_; i += 32) tsh[i] = g_table[i];
    dnsh[lane]      = g_denom[lane];
    dnsh[lane + 32] = g_denom[lane + 32];
    kssh[lane]      = g_ksq[lane];
    kssh[lane + 32] = g_ksq[lane + 32];
    __syncwarp();

    float MA[H_], MB[H_];
#pragma unroll
    for (int j = 0; j < H_; j++) { MA[j] = 0.0f; MB[j] = 0.0f; }

    float eoA = 0.0f, eoB = 0.0f;       // cached ||M||^2 fold (0 exact for M=0)
    bool validA = true, validB = true;

    int writes = 0;
    const int* sA = seq + bA * L_;
    const int* sB = seq + bB * L_;

    for (int t0 = 0; t0 < STEPS; t0 += 32) {
        toksA[lane] = sA[t0 + lane];
        toksB[lane] = sB[t0 + lane];
        __syncwarp();
        const int tend = (STEPS - t0) < 32 ? (STEPS - t0) : 32;

        for (int tt = 0; tt < tend; tt++) {
            const float* kA = tsh + toksA[tt] * H_;
            const float* kB = tsh + toksB[tt] * H_;
            const float dnA = dnsh[toksA[tt]], ksA = kssh[toksA[tt]];
            const float dnB = dnsh[toksB[tt]], ksB = kssh[toksB[tt]];

            const float vA = neon_dot32(MA, kA);
            const float vB = neon_dot32(MB, kB);

            const float uA = __fsub_rn(kA[lane], __fdiv_rn(vA, dnA));
            const float uB = __fsub_rn(kB[lane], __fdiv_rn(vB, dnB));

            float suvA = __fmul_rn(uA, vA);
            float suuA = __fmul_rn(uA, uA);
            float suvB = __fmul_rn(uB, vB);
            float suuB = __fmul_rn(uB, uB);
#pragma unroll
            for (int o = 16; o > 0; o >>= 1) {
                suvA += __shfl_xor_sync(FULL, suvA, o);
                suuA += __shfl_xor_sync(FULL, suuA, o);
                suvB += __shfl_xor_sync(FULL, suvB, o);
                suuB += __shfl_xor_sync(FULL, suuB, o);
            }
            const float dEA = __fadd_rn(__fadd_rn(suvA, suvA), __fmul_rn(suuA, ksA));
            const float dEB = __fadd_rn(__fadd_rn(suvB, suvB), __fmul_rn(suuB, ksB));

            const bool slowA = fabsf(dEA) < THRESH;
            const bool slowB = fabsf(dEB) < THRESH;
            int gateA = dEA > 0.0f;
            int gateB = dEB > 0.0f;

            if (slowA | slowB) {
                if (slowA & slowB & validA & validB) {
                    // paired: A's Mn chain on lanes 0-15, B's on 16-31
                    store_row_mn(mnA, lane, MA, uA, kA);
                    store_row_mn(mnB, lane, MB, uB, kB);
                    __syncwarp();
                    float a = chain64p((lane < 16) ? mnA : mnB, lane & 15);
                    __syncwarp();
                    float enA = fold16(a, 0, FULL);
                    float enB = fold16(a, 16, FULL);
                    gateA = enA > eoA;
                    gateB = enB > eoB;
                    if (gateA) eoA = enA;
                    if (gateB) eoB = enB;
                } else {
                    if (slowA)
                        gateA = resolve_single(MA, uA, kA, eoA, validA, mnA, moA, lane, FULL);
                    if (slowB)
                        gateB = resolve_single(MB, uB, kB, eoB, validB, mnB, moB, lane, FULL);
                }
            }

            if (gateA) {
                writes++;
#pragma unroll
                for (int j = 0; j < H_; j++) MA[j] = fmaf(uA, kA[j], MA[j]);
                if (!slowA) validA = false;
            }
            if (gateB) {
                writes++;
#pragma unroll
                for (int j = 0; j < H_; j++) MB[j] = fmaf(uB, kB[j], MB[j]);
                if (!slowB) validB = false;
            }
        }
        __syncwarp();
    }

    // -------- readout (both batches), identical arithmetic --------
#pragma unroll
    for (int pass = 0; pass < 2; pass++) {
        const int b = pass ? bB : bA;
        const float* M = pass ? MB : MA;
        const int qtok = (pass ? sB : sA)[L_ - 1];
        const float* qv = tsh + qtok * H_;
        float ctx = neon_dot32(M, qv);

        scratch[lane] = ctx;
        __syncwarp();
        float r = 0.0f;
#pragma unroll
        for (int j = 0; j < H_; j++) r = fmaf(scratch[j], w_read[j * H_ + lane], r);
        r = __fadd_rn(r, b_read[lane]);
        __syncwarp();
        scratch[lane] = r;
        __syncwarp();

        float o0 = 0.0f, o1 = 0.0f;
#pragma unroll
        for (int j = 0; j < H_; j++) {
            const float rj = scratch[j];
            o0 = fmaf(rj, w_out[j * V_ + lane], o0);
            o1 = fmaf(rj, w_out[j * V_ + lane + H_], o1);
        }
        out[b * V_ + lane]      = __fadd_rn(o0, b_out[lane]);
        out[b * V_ + lane + H_] = __fadd_rn(o1, b_out[lane + H_]);
        __syncwarp();
    }

    if (lane == 0) atomicAdd(&g_writes, writes);
}

// ---------------------------------------------------------------------------
__global__ void finalize_kernel(float* __restrict__ out, int out_size)
{
    if (out_size > B_ * V_)
        out[B_ * V_] = __fdiv_rn((float)g_writes, (float)(STEPS * B_));
}

extern "C" void kernel_launch(void* const* d_in, const int* in_sizes, int n_in,
                              void* d_out, int out_size)
{
    const int*   seq    = (const int*)d_in[0];
    const float* embed  = (const float*)d_in[1];
    const float* w1     = (const float*)d_in[2];
    const float* b1     = (const float*)d_in[3];
    const float* w2     = (const float*)d_in[4];
    const float* b2     = (const float*)d_in[5];
    const float* ln_g   = (const float*)d_in[6];
    const float* ln_b   = (const float*)d_in[7];
    const float* w_read = (const float*)d_in[8];
    const float* b_read = (const float*)d_in[9];
    const float* w_out  = (const float*)d_in[10];
    const float* b_out  = (const float*)d_in[11];
    float* out = (float*)d_out;

    precompute_kernel<<<V_, 64>>>(embed, w1, b1, w2, b2, ln_g, ln_b);
    scan_kernel<<<B_ / 2, 32>>>(seq, w_read, b_read, w_out, b_out, out);
    finalize_kernel<<<1, 1>>>(out, out_size);
}